// round 17
// baseline (speedup 1.0000x reference)
#include <cuda_runtime.h>
#include <cuda_fp16.h>
#include <cstdint>
#include <cstddef>

// CapsuleLayer, two-kernel version. Round-16 base (146.2us) + K2 occupancy push
// (__launch_bounds__(256,6) -> 40 regs, 48 warps/SM).
//  K1: u_hat = x @ W  (fp16x3, mma.sync m16n8k16, SMEM-staged W, persistent CTAs,
//      2 CTAs/SM, single-barrier double-buffer, dense LDG) -> g_uhat (r,b,c,o)
//  K2: routing, HALF-warp per (b,r), register/shfl.
// B=64, C=32, R=1152, IN=128, OUT=16, ITERS=3.

#define B_      64
#define C_      32
#define R_      1152
#define IN_     128
#define OUT_    16
#define ROWB    80                         // W smem row: 32B hi + 32B lo + 16B pad
#define WTILE_B (IN_ * ROWB)               // one r tile (hi+lo): 10240 B
#define SMEM1_BYTES (2 * 2 * WTILE_B)      // 2 bufs x 2 r-tiles = 40960
#define GEMM_CTAS   288                    // persistent; 8 tasks each (288*8 = 2304)
#define NT1   256
#define CO    (C_ * OUT_)                  // 512 floats: b-stride in (r,b,c,o) layout

__device__ float g_uhat[(size_t)R_ * B_ * C_ * OUT_];   // 151 MB scratch, (r,b,c,o)

__device__ __forceinline__ unsigned h2bits(half2 h) {
    return *reinterpret_cast<unsigned*>(&h);
}
// v = hi + lo with hi,lo fp16 (packed pairs); ~22 effective bits
__device__ __forceinline__ void split2(float vx, float vy, unsigned& h, unsigned& l) {
    half2 hh = __floats2half2_rn(vx, vy);
    float2 hf = __half22float2(hh);
    half2 ll = __floats2half2_rn(vx - hf.x, vy - hf.y);
    h = h2bits(hh);
    l = h2bits(ll);
}

__device__ __forceinline__ void mma16(float& d0, float& d1, float& d2, float& d3,
                                      unsigned a0, unsigned a1, unsigned a2, unsigned a3,
                                      unsigned b0, unsigned b1) {
    asm volatile(
        "mma.sync.aligned.m16n8k16.row.col.f32.f16.f16.f32 "
        "{%0,%1,%2,%3}, {%4,%5,%6,%7}, {%8,%9}, {%0,%1,%2,%3};"
        : "+f"(d0), "+f"(d1), "+f"(d2), "+f"(d3)
        : "r"(a0), "r"(a1), "r"(a2), "r"(a3), "r"(b0), "r"(b1));
}

__device__ __forceinline__ void ldsm4t(unsigned& r0, unsigned& r1, unsigned& r2, unsigned& r3,
                                       unsigned addr) {
    asm volatile("ldmatrix.sync.aligned.m8n8.x4.trans.shared.b16 {%0,%1,%2,%3}, [%4];"
                 : "=r"(r0), "=r"(r1), "=r"(r2), "=r"(r3) : "r"(addr));
}

// ===================== Kernel 1: GEMM -> g_uhat (r,b,c,o) — round-16 verbatim ====
// Task t (0..2303): c = t/72, rb = t%72 -> r block rb*16..rb*16+15.
// CTA does tasks bid*8 .. bid*8+7; 64 stages of 2 r-tiles (r = rb*16 + 2*(s&7) + g).
// Single-barrier double-buffer: STS(s+1) | prefetch(s+2) | MMA(s) | sync.

extern "C" __global__ void __launch_bounds__(NT1, 2)
caps_gemm_kernel(const float* __restrict__ X,      // (B, IN)
                 const float* __restrict__ W)      // (C, R, IN, OUT)
{
    extern __shared__ char wbuf[];                  // 2 bufs x 2 tiles x WTILE_B

    const int bid   = blockIdx.x;
    const int tid   = threadIdx.x;
    const int warp  = tid >> 5;    // 0..7
    const int lane  = tid & 31;
    const int group = lane >> 2;   // 0..7
    const int tig   = lane & 3;    // 0..3
    const int p = warp & 3;
    const int g = warp >> 2;       // 0/1

    // x fragments (fp16 hi/lo), two n-tiles: b = 16p+group / 16p+8+group. Loaded ONCE.
    unsigned xh0[16], xl0[16], xh1[16], xl1[16];
    {
        const float2* xr0 = reinterpret_cast<const float2*>(X) + (size_t)(16 * p + group) * (IN_ / 2);
        const float2* xr1 = reinterpret_cast<const float2*>(X) + (size_t)(16 * p + 8 + group) * (IN_ / 2);
#pragma unroll
        for (int kc = 0; kc < 8; ++kc) {
            float2 v;
            v = __ldg(xr0 + 8 * kc + tig);
            split2(v.x, v.y, xh0[2 * kc], xl0[2 * kc]);
            v = __ldg(xr0 + 8 * kc + tig + 4);
            split2(v.x, v.y, xh0[2 * kc + 1], xl0[2 * kc + 1]);
            v = __ldg(xr1 + 8 * kc + tig);
            split2(v.x, v.y, xh1[2 * kc], xl1[2 * kc]);
            v = __ldg(xr1 + 8 * kc + tig + 4);
            split2(v.x, v.y, xh1[2 * kc + 1], xl1[2 * kc + 1]);
        }
    }

    // Dense-LDG staging: thread t loads float4 at tile-flat offset 4t (rows 0-63)
    // and 4t+1024 (rows 64-127): each warp LDG = 512B contiguous.
    const int i_a  = tid >> 2;             // 0..63
    const int o4   = (tid & 3) << 2;       // 0,4,8,12
    const int ld_a = i_a * OUT_ + o4;      // == 4*tid
    const int ld_b = ld_a + 1024;          // row 64 + i_a
    const int bo_a = i_a * ROWB + o4 * 2;  // STS byte offset (hi at +0, lo at +32)
    const int bo_b = (64 + i_a) * ROWB + o4 * 2;

    const int lm_i = (lane & 7) + ((lane >> 4) << 3);
    const int lm_byte = lm_i * ROWB + ((lane & 8) ? 16 : 0);
    const unsigned wbuf_s = (unsigned)__cvta_generic_to_shared(wbuf);

    auto stage_base = [&](int s) -> const float* {
        int task = bid * 8 + (s >> 3);
        int c  = task / 72;
        int rb = task - c * 72;
        return W + ((size_t)c * R_ + rb * 16 + (s & 7) * 2) * (IN_ * OUT_);
    };

    auto stage_sts = [&](int buf, float4 vA0, float4 vA1, float4 vB0, float4 vB1) {
        char* baseA = wbuf + (size_t)(buf * 2 + 0) * WTILE_B;
        char* baseB = wbuf + (size_t)(buf * 2 + 1) * WTILE_B;
        unsigned h01, l01, h23, l23;
        split2(vA0.x, vA0.y, h01, l01);
        split2(vA0.z, vA0.w, h23, l23);
        *reinterpret_cast<uint2*>(baseA + bo_a)      = make_uint2(h01, h23);
        *reinterpret_cast<uint2*>(baseA + bo_a + 32) = make_uint2(l01, l23);
        split2(vA1.x, vA1.y, h01, l01);
        split2(vA1.z, vA1.w, h23, l23);
        *reinterpret_cast<uint2*>(baseA + bo_b)      = make_uint2(h01, h23);
        *reinterpret_cast<uint2*>(baseA + bo_b + 32) = make_uint2(l01, l23);
        split2(vB0.x, vB0.y, h01, l01);
        split2(vB0.z, vB0.w, h23, l23);
        *reinterpret_cast<uint2*>(baseB + bo_a)      = make_uint2(h01, h23);
        *reinterpret_cast<uint2*>(baseB + bo_a + 32) = make_uint2(l01, l23);
        split2(vB1.x, vB1.y, h01, l01);
        split2(vB1.z, vB1.w, h23, l23);
        *reinterpret_cast<uint2*>(baseB + bo_b)      = make_uint2(h01, h23);
        *reinterpret_cast<uint2*>(baseB + bo_b + 32) = make_uint2(l01, l23);
    };

    float4 vA0, vA1, vB0, vB1;
    {
        const float* Ws = stage_base(0);
        vA0 = __ldg(reinterpret_cast<const float4*>(Ws + ld_a));
        vA1 = __ldg(reinterpret_cast<const float4*>(Ws + ld_b));
        vB0 = __ldg(reinterpret_cast<const float4*>(Ws + 2048 + ld_a));
        vB1 = __ldg(reinterpret_cast<const float4*>(Ws + 2048 + ld_b));
        stage_sts(0, vA0, vA1, vB0, vB1);
        const float* Wn = stage_base(1);
        vA0 = __ldg(reinterpret_cast<const float4*>(Wn + ld_a));
        vA1 = __ldg(reinterpret_cast<const float4*>(Wn + ld_b));
        vB0 = __ldg(reinterpret_cast<const float4*>(Wn + 2048 + ld_a));
        vB1 = __ldg(reinterpret_cast<const float4*>(Wn + 2048 + ld_b));
    }
    __syncthreads();

#pragma unroll 1
    for (int s = 0; s < 64; ++s) {
        if (s < 63)
            stage_sts((s + 1) & 1, vA0, vA1, vB0, vB1);
        if (s < 62) {
            const float* Wn = stage_base(s + 2);
            vA0 = __ldg(reinterpret_cast<const float4*>(Wn + ld_a));
            vA1 = __ldg(reinterpret_cast<const float4*>(Wn + ld_b));
            vB0 = __ldg(reinterpret_cast<const float4*>(Wn + 2048 + ld_a));
            vB1 = __ldg(reinterpret_cast<const float4*>(Wn + 2048 + ld_b));
        }

        const unsigned hbase = wbuf_s + (unsigned)((s & 1) * 2 + g) * WTILE_B + lm_byte;

        float d0 = 0.f, d1 = 0.f, d2 = 0.f, d3 = 0.f;
        float e0 = 0.f, e1 = 0.f, e2 = 0.f, e3 = 0.f;
        float f0 = 0.f, f1 = 0.f, f2 = 0.f, f3 = 0.f;
        float h0 = 0.f, h1 = 0.f, h2 = 0.f, h3 = 0.f;
#pragma unroll
        for (int kc = 0; kc < 8; kc += 2) {
            unsigned ah0, ah1, ah2, ah3, al0, al1, al2, al3;
            unsigned bh0, bh1, bh2, bh3, bl0, bl1, bl2, bl3;
            const unsigned ka = hbase + (unsigned)(16 * kc) * ROWB;
            ldsm4t(ah0, ah1, ah2, ah3, ka);
            ldsm4t(al0, al1, al2, al3, ka + 32);
            ldsm4t(bh0, bh1, bh2, bh3, ka + 16 * ROWB);
            ldsm4t(bl0, bl1, bl2, bl3, ka + 16 * ROWB + 32);
            const int k0 = 2 * kc, k1 = 2 * kc + 2;
            mma16(d0, d1, d2, d3, ah0, ah1, ah2, ah3, xh0[k0], xh0[k0 + 1]);
            mma16(e0, e1, e2, e3, ah0, ah1, ah2, ah3, xh1[k0], xh1[k0 + 1]);
            mma16(f0, f1, f2, f3, bh0, bh1, bh2, bh3, xh0[k1], xh0[k1 + 1]);
            mma16(h0, h1, h2, h3, bh0, bh1, bh2, bh3, xh1[k1], xh1[k1 + 1]);
            mma16(d0, d1, d2, d3, al0, al1, al2, al3, xh0[k0], xh0[k0 + 1]);
            mma16(e0, e1, e2, e3, al0, al1, al2, al3, xh1[k0], xh1[k0 + 1]);
            mma16(f0, f1, f2, f3, bl0, bl1, bl2, bl3, xh0[k1], xh0[k1 + 1]);
            mma16(h0, h1, h2, h3, bl0, bl1, bl2, bl3, xh1[k1], xh1[k1 + 1]);
            mma16(d0, d1, d2, d3, ah0, ah1, ah2, ah3, xl0[k0], xl0[k0 + 1]);
            mma16(e0, e1, e2, e3, ah0, ah1, ah2, ah3, xl1[k0], xl1[k0 + 1]);
            mma16(f0, f1, f2, f3, bh0, bh1, bh2, bh3, xl0[k1], xl0[k1 + 1]);
            mma16(h0, h1, h2, h3, bh0, bh1, bh2, bh3, xl1[k1], xl1[k1 + 1]);
        }
        d0 += f0; d1 += f1; d2 += f2; d3 += f3;
        e0 += h0; e1 += h1; e2 += h2; e3 += h3;

        {
            int task = bid * 8 + (s >> 3);
            int c  = task / 72;
            int rb = task - c * 72;
            int r  = rb * 16 + (s & 7) * 2 + g;
            const int b0 = 16 * p + 2 * tig;
            float* u0 = g_uhat + ((size_t)r * B_ + b0) * CO + c * OUT_ + group;
            u0[0]      = d0;
            u0[CO]     = d1;
            u0[8]      = d2;
            u0[CO + 8] = d3;
            float* u1 = u0 + 8 * CO;
            u1[0]      = e0;
            u1[CO]     = e1;
            u1[8]      = e2;
            u1[CO + 8] = e3;
        }
        __syncthreads();
    }
}

// ===================== Kernel 2: dynamic routing — occ push to 6 blocks/SM ====
// HALF-warp per (b,r): lanes 0-15 pair A, 16-31 pair B. lane = c (two c's per lane).

extern "C" __global__ void __launch_bounds__(256, 6)
caps_route_kernel(float* __restrict__ out)          // (B, R, OUT)
{
    const unsigned FULL = 0xffffffffu;
    const int lane = threadIdx.x & 31;
    const int l16  = lane & 15;
    const int hb   = lane & 16;
    const int pair = (blockIdx.x * 8 + (threadIdx.x >> 5)) * 2 + (lane >> 4);
    const int b = pair / R_;
    const int r = pair - b * R_;

    float uh0[16], uh1[16];
    {
        const float4* up = reinterpret_cast<const float4*>(
            g_uhat + ((size_t)r * B_ + b) * CO + l16 * OUT_);
        float4 v;
        v = __ldg(up + 0);  uh0[0] = v.x;  uh0[1] = v.y;  uh0[2] = v.z;  uh0[3] = v.w;
        v = __ldg(up + 1);  uh0[4] = v.x;  uh0[5] = v.y;  uh0[6] = v.z;  uh0[7] = v.w;
        v = __ldg(up + 2);  uh0[8] = v.x;  uh0[9] = v.y;  uh0[10] = v.z; uh0[11] = v.w;
        v = __ldg(up + 3);  uh0[12] = v.x; uh0[13] = v.y; uh0[14] = v.z; uh0[15] = v.w;
        v = __ldg(up + 64); uh1[0] = v.x;  uh1[1] = v.y;  uh1[2] = v.z;  uh1[3] = v.w;
        v = __ldg(up + 65); uh1[4] = v.x;  uh1[5] = v.y;  uh1[6] = v.z;  uh1[7] = v.w;
        v = __ldg(up + 66); uh1[8] = v.x;  uh1[9] = v.y;  uh1[10] = v.z; uh1[11] = v.w;
        v = __ldg(up + 67); uh1[12] = v.x; uh1[13] = v.y; uh1[14] = v.z; uh1[15] = v.w;
    }

    float blog0 = 0.0f, blog1 = 0.0f;
    const bool h3 = (l16 & 8) != 0;
    const bool h2 = (l16 & 4) != 0;
    const bool h1 = (l16 & 2) != 0;
    const bool h0 = (l16 & 1) != 0;

#pragma unroll 1
    for (int it = 0; it < 3; ++it) {
        float cc0, cc1;
        if (it == 0) {
            cc0 = cc1 = 1.0f / 32.0f;      // softmax of zeros: exactly uniform
        } else {
            float m = fmaxf(blog0, blog1);
#pragma unroll
            for (int s = 8; s > 0; s >>= 1)
                m = fmaxf(m, __shfl_xor_sync(FULL, m, s));
            float e0 = __expf(blog0 - m);
            float e1 = __expf(blog1 - m);
            float Z = e0 + e1;
#pragma unroll
            for (int s = 8; s > 0; s >>= 1)
                Z += __shfl_xor_sync(FULL, Z, s);
            cc0 = e0 / Z;
            cc1 = e1 / Z;
        }

        float q[16];
#pragma unroll
        for (int o = 0; o < 16; ++o)
            q[o] = fmaf(cc1, uh1[o], cc0 * uh0[o]);
#pragma unroll
        for (int i = 0; i < 8; ++i) {
            float snd = h3 ? q[i] : q[i + 8];
            float kp  = h3 ? q[i + 8] : q[i];
            q[i] = kp + __shfl_xor_sync(FULL, snd, 8);
        }
#pragma unroll
        for (int i = 0; i < 4; ++i) {
            float snd = h2 ? q[i] : q[i + 4];
            float kp  = h2 ? q[i + 4] : q[i];
            q[i] = kp + __shfl_xor_sync(FULL, snd, 4);
        }
#pragma unroll
        for (int i = 0; i < 2; ++i) {
            float snd = h1 ? q[i] : q[i + 2];
            float kp  = h1 ? q[i + 2] : q[i];
            q[i] = kp + __shfl_xor_sync(FULL, snd, 2);
        }
        float sv;
        {
            float snd = h0 ? q[0] : q[1];
            float kp  = h0 ? q[1] : q[0];
            sv = kp + __shfl_xor_sync(FULL, snd, 1);
        }

        float n2 = sv * sv;
        n2 += __shfl_xor_sync(FULL, n2, 8);
        n2 += __shfl_xor_sync(FULL, n2, 4);
        n2 += __shfl_xor_sync(FULL, n2, 2);
        n2 += __shfl_xor_sync(FULL, n2, 1);

        const float nrm = sqrtf(n2);
        const float vo  = (n2 / (1.0f + n2)) * (sv / nrm);

        if (it < 2) {
            float a0 = 0.0f, a1 = 0.0f;
#pragma unroll
            for (int o2 = 0; o2 < 16; ++o2) {
                float vv = __shfl_sync(FULL, vo, hb | o2);
                a0 = fmaf(uh0[o2], vv, a0);
                a1 = fmaf(uh1[o2], vv, a1);
            }
            blog0 += a0;
            blog1 += a1;
        } else {
            out[((size_t)b * R_ + r) * OUT_ + l16] = vo;
        }
    }
}

extern "C" void kernel_launch(void* const* d_in, const int* in_sizes, int n_in,
                              void* d_out, int out_size) {
    (void)n_in; (void)out_size;
    const float* a = (const float*)d_in[0];
    const float* b = (const float*)d_in[1];
    const float* X = a;
    const float* W = b;
    if (in_sizes[0] != B_ * IN_) { X = b; W = a; }

    cudaFuncSetAttribute(caps_gemm_kernel,
                         cudaFuncAttributeMaxDynamicSharedMemorySize, SMEM1_BYTES);
    caps_gemm_kernel<<<GEMM_CTAS, NT1, SMEM1_BYTES>>>(X, W);
    caps_route_kernel<<<(B_ * R_) / 16, 256>>>((float*)d_out);
}